// round 12
// baseline (speedup 1.0000x reference)
#include <cuda_runtime.h>
#include <cuda_bf16.h>
#include <cstdint>

// ============================================================
// R12: split-K=4 warp-MMA flash attention, combine folded into attn.
//  - convert_kernel: K,V -> bf16 hi/lo swizzled tiles + mask->float +
//    zeroes the per-(b,qblock) completion counters (replay-safe).
//  - attn kernel: 3-stage cp.async pipeline, 1 sync/tile, PRMT repack;
//    after writing partials, last-arriving CTA of each (b,qblock)
//    normalizes Out = sum_z O_z / sum_z l_z (threadfence-reduction).
// ============================================================

namespace {
constexpr int NQ = 4096, NK = 4096, D = 64, DV = 64, Bb = 8;
constexpr int BM = 128, BN = 64, THREADS = 256;
constexpr int NT = NK / BN;
constexpr int NSPLIT = 4;
constexpr int NTQ = NT / NSPLIT;                // 16 tiles per quarter
constexpr int NQB = NQ / BM;                    // 32 q-blocks
constexpr float QSCALE = 0.18033688011112042f;  // log2(e) / 8

constexpr int ST_KH = 0, ST_KL = 8192, ST_VH = 16384, ST_VL = 24576, ST_MK = 32768;
constexpr int STAGE = 33024;
constexpr int NSTAGE = 3;
constexpr int SMEM_BYTES = NSTAGE * STAGE;      // 99072
}

__device__ __align__(16) uint8_t g_KH[(size_t)Bb * NK * D * 2];
__device__ __align__(16) uint8_t g_KL[(size_t)Bb * NK * D * 2];
__device__ __align__(16) uint8_t g_VH[(size_t)Bb * NK * DV * 2];
__device__ __align__(16) uint8_t g_VL[(size_t)Bb * NK * DV * 2];
__device__ __align__(16) float   g_MKf[(size_t)Bb * NK];
__device__ __align__(16) float   g_Op[(size_t)NSPLIT * Bb * NQ * DV];
__device__ __align__(16) float   g_lp[(size_t)NSPLIT * Bb * NQ];
__device__ int g_cnt[Bb * NQB];

__device__ __forceinline__ uint32_t smem_u32(const void* p) {
  uint32_t a;
  asm("{ .reg .u64 t; cvta.to.shared.u64 t, %1; cvt.u32.u64 %0, t; }" : "=r"(a) : "l"(p));
  return a;
}
__device__ __forceinline__ uint32_t packbf2(__nv_bfloat16 a, __nv_bfloat16 b) {
  __nv_bfloat162 t = __halves2bfloat162(a, b);
  return *reinterpret_cast<uint32_t*>(&t);
}
__device__ __forceinline__ void split2(float x, float y, uint32_t& hi, uint32_t& lo) {
  __nv_bfloat16 hx = __float2bfloat16(x), hy = __float2bfloat16(y);
  hi = packbf2(hx, hy);
  lo = packbf2(__float2bfloat16(x - __bfloat162float(hx)),
               __float2bfloat16(y - __bfloat162float(hy)));
}
// PRMT truncation split for the hot P repack (residual covered by 3rd MMA)
__device__ __forceinline__ void split2t(float x, float y, uint32_t& hi, uint32_t& lo) {
  const uint32_t xb = __float_as_uint(x), yb = __float_as_uint(y);
  asm("prmt.b32 %0, %1, %2, 0x7632;" : "=r"(hi) : "r"(xb), "r"(yb));
  const float xr = x - __uint_as_float(xb & 0xffff0000u);
  const float yr = y - __uint_as_float(yb & 0xffff0000u);
  asm("cvt.rn.bf16x2.f32 %0, %1, %2;" : "=r"(lo) : "f"(yr), "f"(xr));
}
__device__ __forceinline__ float ex2f(float x) {
  float y;
  asm("ex2.approx.ftz.f32 %0, %1;" : "=f"(y) : "f"(x));
  return y;
}
__device__ __forceinline__ void mma16816(float* c, const uint32_t* a,
                                         uint32_t b0, uint32_t b1) {
  asm("mma.sync.aligned.m16n8k16.row.col.f32.bf16.bf16.f32 "
      "{%0,%1,%2,%3}, {%4,%5,%6,%7}, {%8,%9}, {%0,%1,%2,%3};"
      : "+f"(c[0]), "+f"(c[1]), "+f"(c[2]), "+f"(c[3])
      : "r"(a[0]), "r"(a[1]), "r"(a[2]), "r"(a[3]), "r"(b0), "r"(b1));
}
__device__ __forceinline__ void ldsm4(uint32_t a, uint32_t* d) {
  asm volatile("ldmatrix.sync.aligned.m8n8.x4.shared.b16 {%0,%1,%2,%3}, [%4];"
               : "=r"(d[0]), "=r"(d[1]), "=r"(d[2]), "=r"(d[3]) : "r"(a));
}
__device__ __forceinline__ void ldsm4t(uint32_t a, uint32_t* d) {
  asm volatile("ldmatrix.sync.aligned.m8n8.x4.trans.shared.b16 {%0,%1,%2,%3}, [%4];"
               : "=r"(d[0]), "=r"(d[1]), "=r"(d[2]), "=r"(d[3]) : "r"(a));
}
__device__ __forceinline__ void cpasync16(uint32_t dst, const void* src) {
  asm volatile("cp.async.cg.shared.global [%0], [%1], 16;"
               :: "r"(dst), "l"(src) : "memory");
}
#define CP_COMMIT() asm volatile("cp.async.commit_group;" ::: "memory")
#define CP_WAIT1()  asm volatile("cp.async.wait_group 1;"  ::: "memory")

__device__ __forceinline__ uint32_t swz(uint32_t r, uint32_t cbyte) {
  return r * 128u + (cbyte ^ ((r & 7u) * 16u));
}

// ---------------- pre-pass ----------------
__global__ __launch_bounds__(256)
void convert_kernel(const float* __restrict__ K, const float* __restrict__ V,
                    const int* __restrict__ MK) {
  const int idx = blockIdx.x * 256 + threadIdx.x;
  const int n = idx >> 4;
  const int c4 = idx & 15;
  const uint32_t r = (uint32_t)(n & 63);
  const size_t off = (size_t)(n >> 6) * 8192 + swz(r, (uint32_t)c4 * 8u);

  float4 kv = reinterpret_cast<const float4*>(K)[idx];
  uint2 hw, lw;
  split2(kv.x, kv.y, hw.x, lw.x);
  split2(kv.z, kv.w, hw.y, lw.y);
  *reinterpret_cast<uint2*>(g_KH + off) = hw;
  *reinterpret_cast<uint2*>(g_KL + off) = lw;

  float4 vv = reinterpret_cast<const float4*>(V)[idx];
  split2(vv.x, vv.y, hw.x, lw.x);
  split2(vv.z, vv.w, hw.y, lw.y);
  *reinterpret_cast<uint2*>(g_VH + off) = hw;
  *reinterpret_cast<uint2*>(g_VL + off) = lw;

  if (idx < Bb * NK / 4) {
    int4 m = reinterpret_cast<const int4*>(MK)[idx];
    reinterpret_cast<float4*>(g_MKf)[idx] =
        make_float4((float)m.x, (float)m.y, (float)m.z, (float)m.w);
  }
  if (blockIdx.x == 0 && threadIdx.x < Bb * NQB) g_cnt[threadIdx.x] = 0;
}

// ---------------- main attention kernel (combine folded) ----------------
__global__ __launch_bounds__(THREADS, 2)
void attn_mma_kernel(const float* __restrict__ Q, const int* __restrict__ MQ,
                     float* __restrict__ Out) {
  extern __shared__ char smem[];
  const uint32_t sb = smem_u32(smem);
  __shared__ int s_last;

  const int tid = threadIdx.x;
  const int w = tid >> 5, l = tid & 31;
  const int g = l >> 2, tg = l & 3;
  const int b = blockIdx.y;
  const int kq = blockIdx.z;
  const int q0 = blockIdx.x * BM;
  const int row0 = q0 + w * 16 + g;
  const int row1 = row0 + 8;
  const uint32_t lrow = (uint32_t)(l & 7);
  const uint32_t ltile = (uint32_t)(l >> 3);
  const float* MKfb = g_MKf + (size_t)b * NK;

  // ---- Q fragments (persistent), mask*log2e/T folded in
  uint32_t QH[4][4], QL[4][4];
  {
    const float* Qr0 = Q + ((size_t)b * NQ + row0) * D;
    const float* Qr1 = Q + ((size_t)b * NQ + row1) * D;
    const float m0 = MQ[(size_t)b * NQ + row0] ? QSCALE : 0.f;
    const float m1 = MQ[(size_t)b * NQ + row1] ? QSCALE : 0.f;
    #pragma unroll
    for (int ks = 0; ks < 4; ks++) {
      const int c = 16 * ks + 2 * tg;
      float2 v00 = *reinterpret_cast<const float2*>(Qr0 + c);
      float2 v10 = *reinterpret_cast<const float2*>(Qr1 + c);
      float2 v01 = *reinterpret_cast<const float2*>(Qr0 + c + 8);
      float2 v11 = *reinterpret_cast<const float2*>(Qr1 + c + 8);
      split2(v00.x * m0, v00.y * m0, QH[ks][0], QL[ks][0]);
      split2(v10.x * m1, v10.y * m1, QH[ks][1], QL[ks][1]);
      split2(v01.x * m0, v01.y * m0, QH[ks][2], QL[ks][2]);
      split2(v11.x * m1, v11.y * m1, QH[ks][3], QL[ks][3]);
    }
  }

  float O[8][4];
  #pragma unroll
  for (int i = 0; i < 8; i++)
    #pragma unroll
    for (int j = 0; j < 4; j++) O[i][j] = 0.f;
  float l0 = 0.f, l1 = 0.f;

  auto prefetch = [&](int t, int s) {
    const uint32_t dst = sb + (uint32_t)s * STAGE;
    const int tg_ = kq * NTQ + t;
    const size_t toff = (size_t)(b * NT + tg_) * 8192;
    #pragma unroll
    for (int i = 0; i < 2; i++) {
      const uint32_t o = (uint32_t)(tid + i * THREADS) * 16u;
      cpasync16(dst + ST_KH + o, g_KH + toff + o);
      cpasync16(dst + ST_KL + o, g_KL + toff + o);
      cpasync16(dst + ST_VH + o, g_VH + toff + o);
      cpasync16(dst + ST_VL + o, g_VL + toff + o);
    }
    if (tid < 16) cpasync16(dst + ST_MK + tid * 16u, MKfb + tg_ * BN + tid * 4);
  };

  prefetch(0, 0);
  CP_COMMIT();
  prefetch(1, 1);
  CP_COMMIT();

  for (int t = 0; t < NTQ; t++) {
    const int s = t % NSTAGE;
    CP_WAIT1();
    __syncthreads();

    if (t + 2 < NTQ) prefetch(t + 2, (t + 2) % NSTAGE);
    CP_COMMIT();

    const uint32_t skh = sb + (uint32_t)s * STAGE + ST_KH;
    const uint32_t skl = sb + (uint32_t)s * STAGE + ST_KL;
    const uint32_t svh = sb + (uint32_t)s * STAGE + ST_VH;
    const uint32_t svl = sb + (uint32_t)s * STAGE + ST_VL;
    const float* mkf = reinterpret_cast<const float*>(smem + (size_t)s * STAGE + ST_MK);

    float S[8][4];
    #pragma unroll
    for (int i = 0; i < 8; i++)
      #pragma unroll
      for (int j = 0; j < 4; j++) S[i][j] = 0.f;

    #pragma unroll
    for (int nf = 0; nf < 8; nf++) {
      const uint32_t n = 8u * nf + lrow;
      const uint32_t a0 = swz(n, (8u * ltile) * 2u);
      const uint32_t a1 = swz(n, (32u + 8u * ltile) * 2u);
      uint32_t f[8];
      ldsm4(skh + a0, f);
      ldsm4(skh + a1, f + 4);
      #pragma unroll
      for (int ks = 0; ks < 4; ks++) {
        mma16816(S[nf], QH[ks], f[2 * ks], f[2 * ks + 1]);
        mma16816(S[nf], QL[ks], f[2 * ks], f[2 * ks + 1]);
      }
      ldsm4(skl + a0, f);
      ldsm4(skl + a1, f + 4);
      #pragma unroll
      for (int ks = 0; ks < 4; ks++)
        mma16816(S[nf], QH[ks], f[2 * ks], f[2 * ks + 1]);
    }

    #pragma unroll
    for (int ch = 0; ch < 2; ch++) {
      float* Sc = &S[4 * ch][0];

      #pragma unroll
      for (int j = 0; j < 4; j++) {
        const int c0 = 8 * (4 * ch + j) + 2 * tg;
        const float mk0 = mkf[c0], mk1 = mkf[c0 + 1];
        float p0 = ex2f(Sc[4 * j + 0]) * mk0;
        float p1 = ex2f(Sc[4 * j + 1]) * mk1;
        float p2 = ex2f(Sc[4 * j + 2]) * mk0;
        float p3 = ex2f(Sc[4 * j + 3]) * mk1;
        l0 += p0 + p1; l1 += p2 + p3;
        Sc[4 * j + 0] = p0; Sc[4 * j + 1] = p1;
        Sc[4 * j + 2] = p2; Sc[4 * j + 3] = p3;
      }

      uint32_t PH[2][4], PL[2][4];
      #pragma unroll
      for (int j = 0; j < 2; j++) {
        split2t(Sc[8 * j + 0], Sc[8 * j + 1], PH[j][0], PL[j][0]);
        split2t(Sc[8 * j + 2], Sc[8 * j + 3], PH[j][1], PL[j][1]);
        split2t(Sc[8 * j + 4], Sc[8 * j + 5], PH[j][2], PL[j][2]);
        split2t(Sc[8 * j + 6], Sc[8 * j + 7], PH[j][3], PL[j][3]);
      }

      const uint32_t vr = 32u * ch + 8u * ltile + lrow;
      #pragma unroll
      for (int nf = 0; nf < 8; nf++) {
        const uint32_t a = swz(vr, 16u * nf);
        uint32_t fh[4], fl[4];
        ldsm4t(svh + a, fh);
        ldsm4t(svl + a, fl);
        #pragma unroll
        for (int j = 0; j < 2; j++) {
          mma16816(O[nf], PH[j], fh[2 * j], fh[2 * j + 1]);
          mma16816(O[nf], PL[j], fh[2 * j], fh[2 * j + 1]);
          mma16816(O[nf], PH[j], fl[2 * j], fl[2 * j + 1]);
        }
      }
    }
  }

  // ---- write unnormalized partials + partial l
  l0 += __shfl_xor_sync(0xffffffffu, l0, 1);
  l0 += __shfl_xor_sync(0xffffffffu, l0, 2);
  l1 += __shfl_xor_sync(0xffffffffu, l1, 1);
  l1 += __shfl_xor_sync(0xffffffffu, l1, 2);

  const size_t pbase = (size_t)kq * Bb * NQ;
  float* O0 = g_Op + (pbase + (size_t)b * NQ + row0) * DV;
  float* O1 = g_Op + (pbase + (size_t)b * NQ + row1) * DV;
  #pragma unroll
  for (int nf = 0; nf < 8; nf++) {
    const int c = 8 * nf + 2 * tg;
    *reinterpret_cast<float2*>(O0 + c) = make_float2(O[nf][0], O[nf][1]);
    *reinterpret_cast<float2*>(O1 + c) = make_float2(O[nf][2], O[nf][3]);
  }
  if (tg == 0) {
    g_lp[pbase + (size_t)b * NQ + row0] = l0;
    g_lp[pbase + (size_t)b * NQ + row1] = l1;
  }

  // ---- threadfence reduction: last CTA of this (b, qblock) normalizes
  __threadfence();          // each thread's partial stores visible device-wide
  __syncthreads();          // all threads' fences done
  if (tid == 0) s_last = atomicAdd(&g_cnt[b * NQB + blockIdx.x], 1);
  __syncthreads();
  if (s_last == NSPLIT - 1) {
    __threadfence();        // acquire: other CTAs' partials now visible
    // 128 rows x 16 float4 per row = 2048 float4, 256 threads -> 8 each
    #pragma unroll
    for (int it = 0; it < 8; it++) {
      const int i = tid + it * THREADS;
      const int row = i >> 4;                     // 0..127
      const size_t grow = (size_t)b * NQ + q0 + row;
      float4 acc = make_float4(0.f, 0.f, 0.f, 0.f);
      float lsum = 0.f;
      #pragma unroll
      for (int z = 0; z < NSPLIT; z++) {
        float4 v = reinterpret_cast<const float4*>(
            g_Op + ((size_t)z * Bb * NQ + grow) * DV)[i & 15];
        acc.x += v.x; acc.y += v.y; acc.z += v.z; acc.w += v.w;
        lsum += g_lp[(size_t)z * Bb * NQ + grow];
      }
      const float inv = 1.0f / lsum;
      acc.x *= inv; acc.y *= inv; acc.z *= inv; acc.w *= inv;
      reinterpret_cast<float4*>(Out + grow * DV)[i & 15] = acc;
    }
  }
}

extern "C" void kernel_launch(void* const* d_in, const int* in_sizes, int n_in,
                              void* d_out, int out_size) {
  (void)in_sizes; (void)n_in; (void)out_size;
  const float* Q  = (const float*)d_in[0];
  const float* K  = (const float*)d_in[1];
  const float* V  = (const float*)d_in[2];
  const int*   MQ = (const int*)d_in[3];
  const int*   MK = (const int*)d_in[4];
  float* Out = (float*)d_out;

  convert_kernel<<<(Bb * NK * (D / 4)) / 256, 256>>>(K, V, MK);

  cudaFuncSetAttribute(attn_mma_kernel,
                       cudaFuncAttributeMaxDynamicSharedMemorySize, SMEM_BYTES);
  dim3 grid(NQB, Bb, NSPLIT);
  attn_mma_kernel<<<grid, THREADS, SMEM_BYTES>>>(Q, MQ, Out);
}

// round 13
// speedup vs baseline: 1.5395x; 1.5395x over previous
#include <cuda_runtime.h>
#include <cuda_fp16.h>
#include <cuda_bf16.h>
#include <cstdint>

// ============================================================
// R13: revert R12's combine fold (regression); switch to fp16
// 2-product split => 33% fewer MMAs.
//  S  = (Qhi + Qlo) @ K16^T   (K stored as plain fp16; err ~ q*eps_K)
//  O += (Phi + Plo) @ V16     (V stored as plain fp16)
// Q/P hi+lo are exact fp16 splits (residual 2^-22); the dropped terms
// are x*round_err ~ 2.8e-4 rms => total rel_err ~4e-4 < 1e-3.
// 3-stage cp.async pipeline, 1 sync/tile, split-K=4, combine kernel.
// ============================================================

namespace {
constexpr int NQ = 4096, NK = 4096, D = 64, DV = 64, Bb = 8;
constexpr int BM = 128, BN = 64, THREADS = 256;
constexpr int NT = NK / BN;
constexpr int NSPLIT = 4;
constexpr int NTQ = NT / NSPLIT;                // 16 tiles per quarter
constexpr float QSCALE = 0.18033688011112042f;  // log2(e) / 8

constexpr int ST_KH = 0, ST_VH = 8192, ST_MK = 16384;
constexpr int STAGE = 16640;                    // 2*8192 + 256
constexpr int NSTAGE = 3;
constexpr int SMEM_BYTES = NSTAGE * STAGE;      // 49920
}

__device__ __align__(16) uint8_t g_K16[(size_t)Bb * NK * D * 2];   // fp16
__device__ __align__(16) uint8_t g_V16[(size_t)Bb * NK * DV * 2];  // fp16
__device__ __align__(16) float   g_MKf[(size_t)Bb * NK];
__device__ __align__(16) float   g_Op[(size_t)NSPLIT * Bb * NQ * DV];
__device__ __align__(16) float   g_lp[(size_t)NSPLIT * Bb * NQ];

__device__ __forceinline__ uint32_t smem_u32(const void* p) {
  uint32_t a;
  asm("{ .reg .u64 t; cvta.to.shared.u64 t, %1; cvt.u32.u64 %0, t; }" : "=r"(a) : "l"(p));
  return a;
}
// exact fp16 hi/lo split of a float pair (packed half2 words)
__device__ __forceinline__ void split2h(float x, float y, uint32_t& hi, uint32_t& lo) {
  __half2 h = __floats2half2_rn(x, y);
  hi = *reinterpret_cast<uint32_t*>(&h);
  const float rx = x - __half2float(__low2half(h));
  const float ry = y - __half2float(__high2half(h));
  __half2 l2 = __floats2half2_rn(rx, ry);
  lo = *reinterpret_cast<uint32_t*>(&l2);
}
__device__ __forceinline__ uint32_t pack2h(float x, float y) {
  __half2 h = __floats2half2_rn(x, y);
  return *reinterpret_cast<uint32_t*>(&h);
}
__device__ __forceinline__ float ex2f(float x) {
  float y;
  asm("ex2.approx.ftz.f32 %0, %1;" : "=f"(y) : "f"(x));
  return y;
}
__device__ __forceinline__ void mma16816(float* c, const uint32_t* a,
                                         uint32_t b0, uint32_t b1) {
  asm("mma.sync.aligned.m16n8k16.row.col.f32.f16.f16.f32 "
      "{%0,%1,%2,%3}, {%4,%5,%6,%7}, {%8,%9}, {%0,%1,%2,%3};"
      : "+f"(c[0]), "+f"(c[1]), "+f"(c[2]), "+f"(c[3])
      : "r"(a[0]), "r"(a[1]), "r"(a[2]), "r"(a[3]), "r"(b0), "r"(b1));
}
__device__ __forceinline__ void ldsm4(uint32_t a, uint32_t* d) {
  asm volatile("ldmatrix.sync.aligned.m8n8.x4.shared.b16 {%0,%1,%2,%3}, [%4];"
               : "=r"(d[0]), "=r"(d[1]), "=r"(d[2]), "=r"(d[3]) : "r"(a));
}
__device__ __forceinline__ void ldsm4t(uint32_t a, uint32_t* d) {
  asm volatile("ldmatrix.sync.aligned.m8n8.x4.trans.shared.b16 {%0,%1,%2,%3}, [%4];"
               : "=r"(d[0]), "=r"(d[1]), "=r"(d[2]), "=r"(d[3]) : "r"(a));
}
__device__ __forceinline__ void cpasync16(uint32_t dst, const void* src) {
  asm volatile("cp.async.cg.shared.global [%0], [%1], 16;"
               :: "r"(dst), "l"(src) : "memory");
}
#define CP_COMMIT() asm volatile("cp.async.commit_group;" ::: "memory")
#define CP_WAIT1()  asm volatile("cp.async.wait_group 1;"  ::: "memory")

__device__ __forceinline__ uint32_t swz(uint32_t r, uint32_t cbyte) {
  return r * 128u + (cbyte ^ ((r & 7u) * 16u));
}

// ---------------- pre-pass: K,V -> plain fp16 swizzled tiles ----------------
__global__ __launch_bounds__(256)
void convert_kernel(const float* __restrict__ K, const float* __restrict__ V,
                    const int* __restrict__ MK) {
  const int idx = blockIdx.x * 256 + threadIdx.x;
  const int n = idx >> 4;
  const int c4 = idx & 15;
  const uint32_t r = (uint32_t)(n & 63);
  const size_t off = (size_t)(n >> 6) * 8192 + swz(r, (uint32_t)c4 * 8u);

  float4 kv = reinterpret_cast<const float4*>(K)[idx];
  uint2 w;
  w.x = pack2h(kv.x, kv.y);
  w.y = pack2h(kv.z, kv.w);
  *reinterpret_cast<uint2*>(g_K16 + off) = w;

  float4 vv = reinterpret_cast<const float4*>(V)[idx];
  w.x = pack2h(vv.x, vv.y);
  w.y = pack2h(vv.z, vv.w);
  *reinterpret_cast<uint2*>(g_V16 + off) = w;

  if (idx < Bb * NK / 4) {
    int4 m = reinterpret_cast<const int4*>(MK)[idx];
    reinterpret_cast<float4*>(g_MKf)[idx] =
        make_float4((float)m.x, (float)m.y, (float)m.z, (float)m.w);
  }
}

// ---------------- main attention kernel ----------------
__global__ __launch_bounds__(THREADS, 2)
void attn_mma_kernel(const float* __restrict__ Q, const int* __restrict__ MQ) {
  extern __shared__ char smem[];
  const uint32_t sb = smem_u32(smem);

  const int tid = threadIdx.x;
  const int w = tid >> 5, l = tid & 31;
  const int g = l >> 2, tg = l & 3;
  const int b = blockIdx.y;
  const int kq = blockIdx.z;
  const int q0 = blockIdx.x * BM;
  const int row0 = q0 + w * 16 + g;
  const int row1 = row0 + 8;
  const uint32_t lrow = (uint32_t)(l & 7);
  const uint32_t ltile = (uint32_t)(l >> 3);
  const float* MKfb = g_MKf + (size_t)b * NK;

  // ---- Q fragments: exact fp16 hi/lo split of q * mq * log2e/T
  uint32_t QH[4][4], QL[4][4];
  {
    const float* Qr0 = Q + ((size_t)b * NQ + row0) * D;
    const float* Qr1 = Q + ((size_t)b * NQ + row1) * D;
    const float m0 = MQ[(size_t)b * NQ + row0] ? QSCALE : 0.f;
    const float m1 = MQ[(size_t)b * NQ + row1] ? QSCALE : 0.f;
    #pragma unroll
    for (int ks = 0; ks < 4; ks++) {
      const int c = 16 * ks + 2 * tg;
      float2 v00 = *reinterpret_cast<const float2*>(Qr0 + c);
      float2 v10 = *reinterpret_cast<const float2*>(Qr1 + c);
      float2 v01 = *reinterpret_cast<const float2*>(Qr0 + c + 8);
      float2 v11 = *reinterpret_cast<const float2*>(Qr1 + c + 8);
      split2h(v00.x * m0, v00.y * m0, QH[ks][0], QL[ks][0]);
      split2h(v10.x * m1, v10.y * m1, QH[ks][1], QL[ks][1]);
      split2h(v01.x * m0, v01.y * m0, QH[ks][2], QL[ks][2]);
      split2h(v11.x * m1, v11.y * m1, QH[ks][3], QL[ks][3]);
    }
  }

  float O[8][4];
  #pragma unroll
  for (int i = 0; i < 8; i++)
    #pragma unroll
    for (int j = 0; j < 4; j++) O[i][j] = 0.f;
  float l0 = 0.f, l1 = 0.f;

  auto prefetch = [&](int t, int s) {
    const uint32_t dst = sb + (uint32_t)s * STAGE;
    const int tg_ = kq * NTQ + t;
    const size_t toff = (size_t)(b * NT + tg_) * 8192;
    #pragma unroll
    for (int i = 0; i < 2; i++) {
      const uint32_t o = (uint32_t)(tid + i * THREADS) * 16u;
      cpasync16(dst + ST_KH + o, g_K16 + toff + o);
      cpasync16(dst + ST_VH + o, g_V16 + toff + o);
    }
    if (tid < 16) cpasync16(dst + ST_MK + tid * 16u, MKfb + tg_ * BN + tid * 4);
  };

  prefetch(0, 0);
  CP_COMMIT();
  prefetch(1, 1);
  CP_COMMIT();

  for (int t = 0; t < NTQ; t++) {
    const int s = t % NSTAGE;
    CP_WAIT1();
    __syncthreads();

    if (t + 2 < NTQ) prefetch(t + 2, (t + 2) % NSTAGE);
    CP_COMMIT();

    const uint32_t skh = sb + (uint32_t)s * STAGE + ST_KH;
    const uint32_t svh = sb + (uint32_t)s * STAGE + ST_VH;
    const float* mkf = reinterpret_cast<const float*>(smem + (size_t)s * STAGE + ST_MK);

    float S[8][4];
    #pragma unroll
    for (int i = 0; i < 8; i++)
      #pragma unroll
      for (int j = 0; j < 4; j++) S[i][j] = 0.f;

    // ---- S = (Qhi + Qlo) @ K16^T  (2 MMAs per fragment)
    #pragma unroll
    for (int nf = 0; nf < 8; nf++) {
      const uint32_t n = 8u * nf + lrow;
      const uint32_t a0 = swz(n, (8u * ltile) * 2u);
      const uint32_t a1 = swz(n, (32u + 8u * ltile) * 2u);
      uint32_t f[8];
      ldsm4(skh + a0, f);
      ldsm4(skh + a1, f + 4);
      #pragma unroll
      for (int ks = 0; ks < 4; ks++) {
        mma16816(S[nf], QH[ks], f[2 * ks], f[2 * ks + 1]);
        mma16816(S[nf], QL[ks], f[2 * ks], f[2 * ks + 1]);
      }
    }

    // ---- two half-chunks: softmax -> fp16 split repack -> PV
    #pragma unroll
    for (int ch = 0; ch < 2; ch++) {
      float* Sc = &S[4 * ch][0];

      #pragma unroll
      for (int j = 0; j < 4; j++) {
        const int c0 = 8 * (4 * ch + j) + 2 * tg;
        const float mk0 = mkf[c0], mk1 = mkf[c0 + 1];
        float p0 = ex2f(Sc[4 * j + 0]) * mk0;
        float p1 = ex2f(Sc[4 * j + 1]) * mk1;
        float p2 = ex2f(Sc[4 * j + 2]) * mk0;
        float p3 = ex2f(Sc[4 * j + 3]) * mk1;
        l0 += p0 + p1; l1 += p2 + p3;
        Sc[4 * j + 0] = p0; Sc[4 * j + 1] = p1;
        Sc[4 * j + 2] = p2; Sc[4 * j + 3] = p3;
      }

      uint32_t PH[2][4], PL[2][4];
      #pragma unroll
      for (int j = 0; j < 2; j++) {
        split2h(Sc[8 * j + 0], Sc[8 * j + 1], PH[j][0], PL[j][0]);
        split2h(Sc[8 * j + 2], Sc[8 * j + 3], PH[j][1], PL[j][1]);
        split2h(Sc[8 * j + 4], Sc[8 * j + 5], PH[j][2], PL[j][2]);
        split2h(Sc[8 * j + 6], Sc[8 * j + 7], PH[j][3], PL[j][3]);
      }

      const uint32_t vr = 32u * ch + 8u * ltile + lrow;
      #pragma unroll
      for (int nf = 0; nf < 8; nf++) {
        const uint32_t a = swz(vr, 16u * nf);
        uint32_t fh[4];
        ldsm4t(svh + a, fh);
        #pragma unroll
        for (int j = 0; j < 2; j++) {
          mma16816(O[nf], PH[j], fh[2 * j], fh[2 * j + 1]);
          mma16816(O[nf], PL[j], fh[2 * j], fh[2 * j + 1]);
        }
      }
    }
  }

  // ---- write unnormalized partials + partial l
  l0 += __shfl_xor_sync(0xffffffffu, l0, 1);
  l0 += __shfl_xor_sync(0xffffffffu, l0, 2);
  l1 += __shfl_xor_sync(0xffffffffu, l1, 1);
  l1 += __shfl_xor_sync(0xffffffffu, l1, 2);

  const size_t pbase = (size_t)kq * Bb * NQ;
  float* O0 = g_Op + (pbase + (size_t)b * NQ + row0) * DV;
  float* O1 = g_Op + (pbase + (size_t)b * NQ + row1) * DV;
  #pragma unroll
  for (int nf = 0; nf < 8; nf++) {
    const int c = 8 * nf + 2 * tg;
    *reinterpret_cast<float2*>(O0 + c) = make_float2(O[nf][0], O[nf][1]);
    *reinterpret_cast<float2*>(O1 + c) = make_float2(O[nf][2], O[nf][3]);
  }
  if (tg == 0) {
    g_lp[pbase + (size_t)b * NQ + row0] = l0;
    g_lp[pbase + (size_t)b * NQ + row1] = l1;
  }
}

// ---------------- combine: Out = sum_z O_z / sum_z l_z ----------------
__global__ __launch_bounds__(256)
void combine_kernel(float* __restrict__ Out) {
  const int idx = blockIdx.x * 256 + threadIdx.x;
  const int grow = idx >> 4;
  float4 acc = make_float4(0.f, 0.f, 0.f, 0.f);
  float lsum = 0.f;
  #pragma unroll
  for (int z = 0; z < NSPLIT; z++) {
    const size_t o = (size_t)z * Bb * NQ * (DV / 4) + idx;
    float4 v = reinterpret_cast<const float4*>(g_Op)[o];
    acc.x += v.x; acc.y += v.y; acc.z += v.z; acc.w += v.w;
    lsum += g_lp[(size_t)z * Bb * NQ + grow];
  }
  const float inv = 1.0f / lsum;
  acc.x *= inv; acc.y *= inv; acc.z *= inv; acc.w *= inv;
  reinterpret_cast<float4*>(Out)[idx] = acc;
}

extern "C" void kernel_launch(void* const* d_in, const int* in_sizes, int n_in,
                              void* d_out, int out_size) {
  (void)in_sizes; (void)n_in; (void)out_size;
  const float* Q  = (const float*)d_in[0];
  const float* K  = (const float*)d_in[1];
  const float* V  = (const float*)d_in[2];
  const int*   MQ = (const int*)d_in[3];
  const int*   MK = (const int*)d_in[4];
  float* Out = (float*)d_out;

  convert_kernel<<<(Bb * NK * (D / 4)) / 256, 256>>>(K, V, MK);

  cudaFuncSetAttribute(attn_mma_kernel,
                       cudaFuncAttributeMaxDynamicSharedMemorySize, SMEM_BYTES);
  dim3 grid(NQ / BM, Bb, NSPLIT);
  attn_mma_kernel<<<grid, THREADS, SMEM_BYTES>>>(Q, MQ);

  combine_kernel<<<(Bb * NQ * DV / 4) / 256, 256>>>(Out);
}

// round 14
// speedup vs baseline: 2.4043x; 1.5617x over previous
#include <cuda_runtime.h>
#include <cuda_fp16.h>
#include <cstdint>

// ============================================================
// R14: pure-fp16 warp-MMA flash attention (fp32 accumulate).
//  S  = Q16 @ K16^T    (1 MMA per fragment; Q,K rounded to fp16)
//  O += P16 @ V16      (1 MMA per fragment; P rounded to fp16)
// Calibrated error model (R13 measured 2.9e-4 with K,V rounded):
// adding Q,P rounding => ~5e-4 total, 2x margin under 1e-3.
// Split-K=4, 3-stage cp.async pipeline, 1 sync/tile, combine kernel.
// ============================================================

namespace {
constexpr int NQ = 4096, NK = 4096, D = 64, DV = 64, Bb = 8;
constexpr int BM = 128, BN = 64, THREADS = 256;
constexpr int NT = NK / BN;
constexpr int NSPLIT = 4;
constexpr int NTQ = NT / NSPLIT;                // 16 tiles per quarter
constexpr float QSCALE = 0.18033688011112042f;  // log2(e) / 8

constexpr int ST_KH = 0, ST_VH = 8192, ST_MK = 16384;
constexpr int STAGE = 16640;                    // 2*8192 + 256
constexpr int NSTAGE = 3;
constexpr int SMEM_BYTES = NSTAGE * STAGE;      // 49920
}

__device__ __align__(16) uint8_t g_K16[(size_t)Bb * NK * D * 2];   // fp16
__device__ __align__(16) uint8_t g_V16[(size_t)Bb * NK * DV * 2];  // fp16
__device__ __align__(16) float   g_MKf[(size_t)Bb * NK];
__device__ __align__(16) float   g_Op[(size_t)NSPLIT * Bb * NQ * DV];
__device__ __align__(16) float   g_lp[(size_t)NSPLIT * Bb * NQ];

__device__ __forceinline__ uint32_t smem_u32(const void* p) {
  uint32_t a;
  asm("{ .reg .u64 t; cvta.to.shared.u64 t, %1; cvt.u32.u64 %0, t; }" : "=r"(a) : "l"(p));
  return a;
}
__device__ __forceinline__ uint32_t pack2h(float x, float y) {
  __half2 h = __floats2half2_rn(x, y);
  return *reinterpret_cast<uint32_t*>(&h);
}
__device__ __forceinline__ float ex2f(float x) {
  float y;
  asm("ex2.approx.ftz.f32 %0, %1;" : "=f"(y) : "f"(x));
  return y;
}
__device__ __forceinline__ void mma16816(float* c, const uint32_t* a,
                                         uint32_t b0, uint32_t b1) {
  asm("mma.sync.aligned.m16n8k16.row.col.f32.f16.f16.f32 "
      "{%0,%1,%2,%3}, {%4,%5,%6,%7}, {%8,%9}, {%0,%1,%2,%3};"
      : "+f"(c[0]), "+f"(c[1]), "+f"(c[2]), "+f"(c[3])
      : "r"(a[0]), "r"(a[1]), "r"(a[2]), "r"(a[3]), "r"(b0), "r"(b1));
}
__device__ __forceinline__ void ldsm4(uint32_t a, uint32_t* d) {
  asm volatile("ldmatrix.sync.aligned.m8n8.x4.shared.b16 {%0,%1,%2,%3}, [%4];"
               : "=r"(d[0]), "=r"(d[1]), "=r"(d[2]), "=r"(d[3]) : "r"(a));
}
__device__ __forceinline__ void ldsm4t(uint32_t a, uint32_t* d) {
  asm volatile("ldmatrix.sync.aligned.m8n8.x4.trans.shared.b16 {%0,%1,%2,%3}, [%4];"
               : "=r"(d[0]), "=r"(d[1]), "=r"(d[2]), "=r"(d[3]) : "r"(a));
}
__device__ __forceinline__ void cpasync16(uint32_t dst, const void* src) {
  asm volatile("cp.async.cg.shared.global [%0], [%1], 16;"
               :: "r"(dst), "l"(src) : "memory");
}
#define CP_COMMIT() asm volatile("cp.async.commit_group;" ::: "memory")
#define CP_WAIT1()  asm volatile("cp.async.wait_group 1;"  ::: "memory")

__device__ __forceinline__ uint32_t swz(uint32_t r, uint32_t cbyte) {
  return r * 128u + (cbyte ^ ((r & 7u) * 16u));
}

// ---------------- pre-pass: K,V -> fp16 swizzled tiles ----------------
__global__ __launch_bounds__(256)
void convert_kernel(const float* __restrict__ K, const float* __restrict__ V,
                    const int* __restrict__ MK) {
  const int idx = blockIdx.x * 256 + threadIdx.x;
  const int n = idx >> 4;
  const int c4 = idx & 15;
  const uint32_t r = (uint32_t)(n & 63);
  const size_t off = (size_t)(n >> 6) * 8192 + swz(r, (uint32_t)c4 * 8u);

  float4 kv = reinterpret_cast<const float4*>(K)[idx];
  uint2 w;
  w.x = pack2h(kv.x, kv.y);
  w.y = pack2h(kv.z, kv.w);
  *reinterpret_cast<uint2*>(g_K16 + off) = w;

  float4 vv = reinterpret_cast<const float4*>(V)[idx];
  w.x = pack2h(vv.x, vv.y);
  w.y = pack2h(vv.z, vv.w);
  *reinterpret_cast<uint2*>(g_V16 + off) = w;

  if (idx < Bb * NK / 4) {
    int4 m = reinterpret_cast<const int4*>(MK)[idx];
    reinterpret_cast<float4*>(g_MKf)[idx] =
        make_float4((float)m.x, (float)m.y, (float)m.z, (float)m.w);
  }
}

// ---------------- main attention kernel ----------------
__global__ __launch_bounds__(THREADS, 2)
void attn_mma_kernel(const float* __restrict__ Q, const int* __restrict__ MQ) {
  extern __shared__ char smem[];
  const uint32_t sb = smem_u32(smem);

  const int tid = threadIdx.x;
  const int w = tid >> 5, l = tid & 31;
  const int g = l >> 2, tg = l & 3;
  const int b = blockIdx.y;
  const int kq = blockIdx.z;
  const int q0 = blockIdx.x * BM;
  const int row0 = q0 + w * 16 + g;
  const int row1 = row0 + 8;
  const uint32_t lrow = (uint32_t)(l & 7);
  const uint32_t ltile = (uint32_t)(l >> 3);
  const float* MKfb = g_MKf + (size_t)b * NK;

  // ---- Q fragments: fp16 of q * mq * log2e/T
  uint32_t QH[4][4];
  {
    const float* Qr0 = Q + ((size_t)b * NQ + row0) * D;
    const float* Qr1 = Q + ((size_t)b * NQ + row1) * D;
    const float m0 = MQ[(size_t)b * NQ + row0] ? QSCALE : 0.f;
    const float m1 = MQ[(size_t)b * NQ + row1] ? QSCALE : 0.f;
    #pragma unroll
    for (int ks = 0; ks < 4; ks++) {
      const int c = 16 * ks + 2 * tg;
      float2 v00 = *reinterpret_cast<const float2*>(Qr0 + c);
      float2 v10 = *reinterpret_cast<const float2*>(Qr1 + c);
      float2 v01 = *reinterpret_cast<const float2*>(Qr0 + c + 8);
      float2 v11 = *reinterpret_cast<const float2*>(Qr1 + c + 8);
      QH[ks][0] = pack2h(v00.x * m0, v00.y * m0);
      QH[ks][1] = pack2h(v10.x * m1, v10.y * m1);
      QH[ks][2] = pack2h(v01.x * m0, v01.y * m0);
      QH[ks][3] = pack2h(v11.x * m1, v11.y * m1);
    }
  }

  float O[8][4];
  #pragma unroll
  for (int i = 0; i < 8; i++)
    #pragma unroll
    for (int j = 0; j < 4; j++) O[i][j] = 0.f;
  float l0 = 0.f, l1 = 0.f;

  auto prefetch = [&](int t, int s) {
    const uint32_t dst = sb + (uint32_t)s * STAGE;
    const int tg_ = kq * NTQ + t;
    const size_t toff = (size_t)(b * NT + tg_) * 8192;
    #pragma unroll
    for (int i = 0; i < 2; i++) {
      const uint32_t o = (uint32_t)(tid + i * THREADS) * 16u;
      cpasync16(dst + ST_KH + o, g_K16 + toff + o);
      cpasync16(dst + ST_VH + o, g_V16 + toff + o);
    }
    if (tid < 16) cpasync16(dst + ST_MK + tid * 16u, MKfb + tg_ * BN + tid * 4);
  };

  prefetch(0, 0);
  CP_COMMIT();
  prefetch(1, 1);
  CP_COMMIT();

  for (int t = 0; t < NTQ; t++) {
    const int s = t % NSTAGE;
    CP_WAIT1();
    __syncthreads();

    if (t + 2 < NTQ) prefetch(t + 2, (t + 2) % NSTAGE);
    CP_COMMIT();

    const uint32_t skh = sb + (uint32_t)s * STAGE + ST_KH;
    const uint32_t svh = sb + (uint32_t)s * STAGE + ST_VH;
    const float* mkf = reinterpret_cast<const float*>(smem + (size_t)s * STAGE + ST_MK);

    float S[8][4];
    #pragma unroll
    for (int i = 0; i < 8; i++)
      #pragma unroll
      for (int j = 0; j < 4; j++) S[i][j] = 0.f;

    // ---- S = Q16 @ K16^T  (1 MMA per fragment)
    #pragma unroll
    for (int nf = 0; nf < 8; nf++) {
      const uint32_t n = 8u * nf + lrow;
      const uint32_t a0 = swz(n, (8u * ltile) * 2u);
      const uint32_t a1 = swz(n, (32u + 8u * ltile) * 2u);
      uint32_t f[8];
      ldsm4(skh + a0, f);
      ldsm4(skh + a1, f + 4);
      #pragma unroll
      for (int ks = 0; ks < 4; ks++)
        mma16816(S[nf], QH[ks], f[2 * ks], f[2 * ks + 1]);
    }

    // ---- two half-chunks: softmax -> fp16 pack -> PV
    #pragma unroll
    for (int ch = 0; ch < 2; ch++) {
      float* Sc = &S[4 * ch][0];

      #pragma unroll
      for (int j = 0; j < 4; j++) {
        const int c0 = 8 * (4 * ch + j) + 2 * tg;
        const float mk0 = mkf[c0], mk1 = mkf[c0 + 1];
        float p0 = ex2f(Sc[4 * j + 0]) * mk0;
        float p1 = ex2f(Sc[4 * j + 1]) * mk1;
        float p2 = ex2f(Sc[4 * j + 2]) * mk0;
        float p3 = ex2f(Sc[4 * j + 3]) * mk1;
        l0 += p0 + p1; l1 += p2 + p3;
        Sc[4 * j + 0] = p0; Sc[4 * j + 1] = p1;
        Sc[4 * j + 2] = p2; Sc[4 * j + 3] = p3;
      }

      uint32_t PH[2][4];
      #pragma unroll
      for (int j = 0; j < 2; j++) {
        PH[j][0] = pack2h(Sc[8 * j + 0], Sc[8 * j + 1]);
        PH[j][1] = pack2h(Sc[8 * j + 2], Sc[8 * j + 3]);
        PH[j][2] = pack2h(Sc[8 * j + 4], Sc[8 * j + 5]);
        PH[j][3] = pack2h(Sc[8 * j + 6], Sc[8 * j + 7]);
      }

      const uint32_t vr = 32u * ch + 8u * ltile + lrow;
      #pragma unroll
      for (int nf = 0; nf < 8; nf++) {
        const uint32_t a = swz(vr, 16u * nf);
        uint32_t fh[4];
        ldsm4t(svh + a, fh);
        #pragma unroll
        for (int j = 0; j < 2; j++)
          mma16816(O[nf], PH[j], fh[2 * j], fh[2 * j + 1]);
      }
    }
  }

  // ---- write unnormalized partials + partial l
  l0 += __shfl_xor_sync(0xffffffffu, l0, 1);
  l0 += __shfl_xor_sync(0xffffffffu, l0, 2);
  l1 += __shfl_xor_sync(0xffffffffu, l1, 1);
  l1 += __shfl_xor_sync(0xffffffffu, l1, 2);

  const size_t pbase = (size_t)kq * Bb * NQ;
  float* O0 = g_Op + (pbase + (size_t)b * NQ + row0) * DV;
  float* O1 = g_Op + (pbase + (size_t)b * NQ + row1) * DV;
  #pragma unroll
  for (int nf = 0; nf < 8; nf++) {
    const int c = 8 * nf + 2 * tg;
    *reinterpret_cast<float2*>(O0 + c) = make_float2(O[nf][0], O[nf][1]);
    *reinterpret_cast<float2*>(O1 + c) = make_float2(O[nf][2], O[nf][3]);
  }
  if (tg == 0) {
    g_lp[pbase + (size_t)b * NQ + row0] = l0;
    g_lp[pbase + (size_t)b * NQ + row1] = l1;
  }
}

// ---------------- combine: Out = sum_z O_z / sum_z l_z ----------------
__global__ __launch_bounds__(256)
void combine_kernel(float* __restrict__ Out) {
  const int idx = blockIdx.x * 256 + threadIdx.x;
  const int grow = idx >> 4;
  float4 acc = make_float4(0.f, 0.f, 0.f, 0.f);
  float lsum = 0.f;
  #pragma unroll
  for (int z = 0; z < NSPLIT; z++) {
    const size_t o = (size_t)z * Bb * NQ * (DV / 4) + idx;
    float4 v = reinterpret_cast<const float4*>(g_Op)[o];
    acc.x += v.x; acc.y += v.y; acc.z += v.z; acc.w += v.w;
    lsum += g_lp[(size_t)z * Bb * NQ + grow];
  }
  const float inv = 1.0f / lsum;
  acc.x *= inv; acc.y *= inv; acc.z *= inv; acc.w *= inv;
  reinterpret_cast<float4*>(Out)[idx] = acc;
}

extern "C" void kernel_launch(void* const* d_in, const int* in_sizes, int n_in,
                              void* d_out, int out_size) {
  (void)in_sizes; (void)n_in; (void)out_size;
  const float* Q  = (const float*)d_in[0];
  const float* K  = (const float*)d_in[1];
  const float* V  = (const float*)d_in[2];
  const int*   MQ = (const int*)d_in[3];
  const int*   MK = (const int*)d_in[4];
  float* Out = (float*)d_out;

  convert_kernel<<<(Bb * NK * (D / 4)) / 256, 256>>>(K, V, MK);

  cudaFuncSetAttribute(attn_mma_kernel,
                       cudaFuncAttributeMaxDynamicSharedMemorySize, SMEM_BYTES);
  dim3 grid(NQ / BM, Bb, NSPLIT);
  attn_mma_kernel<<<grid, THREADS, SMEM_BYTES>>>(Q, MQ);

  combine_kernel<<<(Bb * NQ * DV / 4) / 256, 256>>>(Out);
}

// round 15
// speedup vs baseline: 2.6188x; 1.0892x over previous
#include <cuda_runtime.h>
#include <cuda_fp16.h>
#include <cstdint>

// ============================================================
// R15: masks moved into the GEMMs.
//  - convert: V' = V * mask_key (fp16), K fp16, plus a per-tile 64x8
//    "mask column" fp16 tile MC (col0 = mk, rest 0).
//  - attn hot loop: p = exp2(S) only (no mask mul, no scalar l);
//    O  += P @ V'          (masked keys auto-zeroed)
//    l   = P @ MC (col 0)  (4 extra MMAs per tile, fp32 accum)
//  Split-K=4, 3-stage cp.async pipeline, 1 sync/tile, combine kernel.
// ============================================================

namespace {
constexpr int NQ = 4096, NK = 4096, D = 64, DV = 64, Bb = 8;
constexpr int BM = 128, BN = 64, THREADS = 256;
constexpr int NT = NK / BN;
constexpr int NSPLIT = 4;
constexpr int NTQ = NT / NSPLIT;                // 16 tiles per quarter
constexpr float QSCALE = 0.18033688011112042f;  // log2(e) / 8

constexpr int ST_K = 0, ST_V = 8192, ST_MC = 16384;
constexpr int STAGE = 17408;                    // 2*8192 + 1024
constexpr int NSTAGE = 3;
constexpr int SMEM_BYTES = NSTAGE * STAGE;      // 52224
}

__device__ __align__(16) uint8_t g_K16[(size_t)Bb * NK * D * 2];   // fp16
__device__ __align__(16) uint8_t g_V16[(size_t)Bb * NK * DV * 2];  // fp16, pre-masked
__device__ __align__(16) uint8_t g_MC[(size_t)Bb * NK * 16];       // 64x8 fp16 mask-col tiles
__device__ __align__(16) float   g_Op[(size_t)NSPLIT * Bb * NQ * DV];
__device__ __align__(16) float   g_lp[(size_t)NSPLIT * Bb * NQ];

__device__ __forceinline__ uint32_t smem_u32(const void* p) {
  uint32_t a;
  asm("{ .reg .u64 t; cvta.to.shared.u64 t, %1; cvt.u32.u64 %0, t; }" : "=r"(a) : "l"(p));
  return a;
}
__device__ __forceinline__ uint32_t pack2h(float x, float y) {
  __half2 h = __floats2half2_rn(x, y);
  return *reinterpret_cast<uint32_t*>(&h);
}
__device__ __forceinline__ float ex2f(float x) {
  float y;
  asm("ex2.approx.ftz.f32 %0, %1;" : "=f"(y) : "f"(x));
  return y;
}
__device__ __forceinline__ void mma16816(float* c, const uint32_t* a,
                                         uint32_t b0, uint32_t b1) {
  asm("mma.sync.aligned.m16n8k16.row.col.f32.f16.f16.f32 "
      "{%0,%1,%2,%3}, {%4,%5,%6,%7}, {%8,%9}, {%0,%1,%2,%3};"
      : "+f"(c[0]), "+f"(c[1]), "+f"(c[2]), "+f"(c[3])
      : "r"(a[0]), "r"(a[1]), "r"(a[2]), "r"(a[3]), "r"(b0), "r"(b1));
}
__device__ __forceinline__ void ldsm4(uint32_t a, uint32_t* d) {
  asm volatile("ldmatrix.sync.aligned.m8n8.x4.shared.b16 {%0,%1,%2,%3}, [%4];"
               : "=r"(d[0]), "=r"(d[1]), "=r"(d[2]), "=r"(d[3]) : "r"(a));
}
__device__ __forceinline__ void ldsm4t(uint32_t a, uint32_t* d) {
  asm volatile("ldmatrix.sync.aligned.m8n8.x4.trans.shared.b16 {%0,%1,%2,%3}, [%4];"
               : "=r"(d[0]), "=r"(d[1]), "=r"(d[2]), "=r"(d[3]) : "r"(a));
}
__device__ __forceinline__ void cpasync16(uint32_t dst, const void* src) {
  asm volatile("cp.async.cg.shared.global [%0], [%1], 16;"
               :: "r"(dst), "l"(src) : "memory");
}
#define CP_COMMIT() asm volatile("cp.async.commit_group;" ::: "memory")
#define CP_WAIT1()  asm volatile("cp.async.wait_group 1;"  ::: "memory")

__device__ __forceinline__ uint32_t swz(uint32_t r, uint32_t cbyte) {
  return r * 128u + (cbyte ^ ((r & 7u) * 16u));
}

// ---------------- pre-pass ----------------
__global__ __launch_bounds__(256)
void convert_kernel(const float* __restrict__ K, const float* __restrict__ V,
                    const int* __restrict__ MK) {
  const int idx = blockIdx.x * 256 + threadIdx.x;   // one float4 of K and V
  const int n = idx >> 4;                           // global key row b*NK + k
  const int c4 = idx & 15;
  const uint32_t r = (uint32_t)(n & 63);
  const size_t off = (size_t)(n >> 6) * 8192 + swz(r, (uint32_t)c4 * 8u);

  float4 kv = reinterpret_cast<const float4*>(K)[idx];
  uint2 w;
  w.x = pack2h(kv.x, kv.y);
  w.y = pack2h(kv.z, kv.w);
  *reinterpret_cast<uint2*>(g_K16 + off) = w;

  const float mk = (float)MK[n];                    // broadcast within 16 threads
  float4 vv = reinterpret_cast<const float4*>(V)[idx];
  w.x = pack2h(vv.x * mk, vv.y * mk);
  w.y = pack2h(vv.z * mk, vv.w * mk);
  *reinterpret_cast<uint2*>(g_V16 + off) = w;

  // mask-column tiles: one 16B row per key (col0 = mk, rest 0)
  if (idx < Bb * NK) {
    const float mrow = (float)MK[idx];
    uint4 mc;
    mc.x = pack2h(mrow, 0.f);
    mc.y = 0u; mc.z = 0u; mc.w = 0u;
    *reinterpret_cast<uint4*>(g_MC + (size_t)idx * 16) = mc;
  }
}

// ---------------- main attention kernel ----------------
__global__ __launch_bounds__(THREADS, 2)
void attn_mma_kernel(const float* __restrict__ Q, const int* __restrict__ MQ) {
  extern __shared__ char smem[];
  const uint32_t sb = smem_u32(smem);

  const int tid = threadIdx.x;
  const int w = tid >> 5, l = tid & 31;
  const int g = l >> 2, tg = l & 3;
  const int b = blockIdx.y;
  const int kq = blockIdx.z;
  const int q0 = blockIdx.x * BM;
  const int row0 = q0 + w * 16 + g;
  const int row1 = row0 + 8;
  const uint32_t lrow = (uint32_t)(l & 7);
  const uint32_t ltile = (uint32_t)(l >> 3);

  // ---- Q fragments: fp16 of q * mq * log2e/T
  uint32_t QH[4][4];
  {
    const float* Qr0 = Q + ((size_t)b * NQ + row0) * D;
    const float* Qr1 = Q + ((size_t)b * NQ + row1) * D;
    const float m0 = MQ[(size_t)b * NQ + row0] ? QSCALE : 0.f;
    const float m1 = MQ[(size_t)b * NQ + row1] ? QSCALE : 0.f;
    #pragma unroll
    for (int ks = 0; ks < 4; ks++) {
      const int c = 16 * ks + 2 * tg;
      float2 v00 = *reinterpret_cast<const float2*>(Qr0 + c);
      float2 v10 = *reinterpret_cast<const float2*>(Qr1 + c);
      float2 v01 = *reinterpret_cast<const float2*>(Qr0 + c + 8);
      float2 v11 = *reinterpret_cast<const float2*>(Qr1 + c + 8);
      QH[ks][0] = pack2h(v00.x * m0, v00.y * m0);
      QH[ks][1] = pack2h(v10.x * m1, v10.y * m1);
      QH[ks][2] = pack2h(v01.x * m0, v01.y * m0);
      QH[ks][3] = pack2h(v11.x * m1, v11.y * m1);
    }
  }

  float O[8][4], Ol[4];
  #pragma unroll
  for (int i = 0; i < 8; i++)
    #pragma unroll
    for (int j = 0; j < 4; j++) O[i][j] = 0.f;
  #pragma unroll
  for (int j = 0; j < 4; j++) Ol[j] = 0.f;

  auto prefetch = [&](int t, int s) {
    const uint32_t dst = sb + (uint32_t)s * STAGE;
    const int tg_ = kq * NTQ + t;
    const size_t toff = (size_t)(b * NT + tg_) * 8192;
    #pragma unroll
    for (int i = 0; i < 2; i++) {
      const uint32_t o = (uint32_t)(tid + i * THREADS) * 16u;
      cpasync16(dst + ST_K + o, g_K16 + toff + o);
      cpasync16(dst + ST_V + o, g_V16 + toff + o);
    }
    if (tid < 64)
      cpasync16(dst + ST_MC + tid * 16u,
                g_MC + (size_t)(b * NT + tg_) * 1024 + tid * 16u);
  };

  prefetch(0, 0);
  CP_COMMIT();
  prefetch(1, 1);
  CP_COMMIT();

  for (int t = 0; t < NTQ; t++) {
    const int s = t % NSTAGE;
    CP_WAIT1();
    __syncthreads();

    if (t + 2 < NTQ) prefetch(t + 2, (t + 2) % NSTAGE);
    CP_COMMIT();

    const uint32_t skh = sb + (uint32_t)s * STAGE + ST_K;
    const uint32_t svh = sb + (uint32_t)s * STAGE + ST_V;
    const uint32_t smc = sb + (uint32_t)s * STAGE + ST_MC;

    float S[8][4];
    #pragma unroll
    for (int i = 0; i < 8; i++)
      #pragma unroll
      for (int j = 0; j < 4; j++) S[i][j] = 0.f;

    // ---- S = Q16 @ K16^T
    #pragma unroll
    for (int nf = 0; nf < 8; nf++) {
      const uint32_t n = 8u * nf + lrow;
      const uint32_t a0 = swz(n, (8u * ltile) * 2u);
      const uint32_t a1 = swz(n, (32u + 8u * ltile) * 2u);
      uint32_t f[8];
      ldsm4(skh + a0, f);
      ldsm4(skh + a1, f + 4);
      #pragma unroll
      for (int ks = 0; ks < 4; ks++)
        mma16816(S[nf], QH[ks], f[2 * ks], f[2 * ks + 1]);
    }

    // ---- two half-chunks: p = exp2(S); pack; PV + l-column MMA
    #pragma unroll
    for (int ch = 0; ch < 2; ch++) {
      float* Sc = &S[4 * ch][0];

      #pragma unroll
      for (int j = 0; j < 16; j++) Sc[j] = ex2f(Sc[j]);

      uint32_t PH[2][4];
      #pragma unroll
      for (int j = 0; j < 2; j++) {
        PH[j][0] = pack2h(Sc[8 * j + 0], Sc[8 * j + 1]);
        PH[j][1] = pack2h(Sc[8 * j + 2], Sc[8 * j + 3]);
        PH[j][2] = pack2h(Sc[8 * j + 4], Sc[8 * j + 5]);
        PH[j][3] = pack2h(Sc[8 * j + 6], Sc[8 * j + 7]);
      }

      const uint32_t vr = 32u * ch + 8u * ltile + lrow;

      // l-column: B fragments from the 64x8 mask tile (16B rows, linear)
      uint32_t fm[4];
      ldsm4t(smc + vr * 16u, fm);
      #pragma unroll
      for (int j = 0; j < 2; j++)
        mma16816(Ol, PH[j], fm[2 * j], fm[2 * j + 1]);

      #pragma unroll
      for (int nf = 0; nf < 8; nf++) {
        const uint32_t a = swz(vr, 16u * nf);
        uint32_t fh[4];
        ldsm4t(svh + a, fh);
        #pragma unroll
        for (int j = 0; j < 2; j++)
          mma16816(O[nf], PH[j], fh[2 * j], fh[2 * j + 1]);
      }
    }
  }

  // ---- write unnormalized partials + partial l (col 0 of Ol, tg==0 lanes)
  const size_t pbase = (size_t)kq * Bb * NQ;
  float* O0 = g_Op + (pbase + (size_t)b * NQ + row0) * DV;
  float* O1 = g_Op + (pbase + (size_t)b * NQ + row1) * DV;
  #pragma unroll
  for (int nf = 0; nf < 8; nf++) {
    const int c = 8 * nf + 2 * tg;
    *reinterpret_cast<float2*>(O0 + c) = make_float2(O[nf][0], O[nf][1]);
    *reinterpret_cast<float2*>(O1 + c) = make_float2(O[nf][2], O[nf][3]);
  }
  if (tg == 0) {
    g_lp[pbase + (size_t)b * NQ + row0] = Ol[0];
    g_lp[pbase + (size_t)b * NQ + row1] = Ol[2];
  }
}

// ---------------- combine: Out = sum_z O_z / sum_z l_z ----------------
__global__ __launch_bounds__(256)
void combine_kernel(float* __restrict__ Out) {
  const int idx = blockIdx.x * 256 + threadIdx.x;
  const int grow = idx >> 4;
  float4 acc = make_float4(0.f, 0.f, 0.f, 0.f);
  float lsum = 0.f;
  #pragma unroll
  for (int z = 0; z < NSPLIT; z++) {
    const size_t o = (size_t)z * Bb * NQ * (DV / 4) + idx;
    float4 v = reinterpret_cast<const float4*>(g_Op)[o];
    acc.x += v.x; acc.y += v.y; acc.z += v.z; acc.w += v.w;
    lsum += g_lp[(size_t)z * Bb * NQ + grow];
  }
  const float inv = 1.0f / lsum;
  acc.x *= inv; acc.y *= inv; acc.z *= inv; acc.w *= inv;
  reinterpret_cast<float4*>(Out)[idx] = acc;
}

extern "C" void kernel_launch(void* const* d_in, const int* in_sizes, int n_in,
                              void* d_out, int out_size) {
  (void)in_sizes; (void)n_in; (void)out_size;
  const float* Q  = (const float*)d_in[0];
  const float* K  = (const float*)d_in[1];
  const float* V  = (const float*)d_in[2];
  const int*   MQ = (const int*)d_in[3];
  const int*   MK = (const int*)d_in[4];
  float* Out = (float*)d_out;

  convert_kernel<<<(Bb * NK * (D / 4)) / 256, 256>>>(K, V, MK);

  cudaFuncSetAttribute(attn_mma_kernel,
                       cudaFuncAttributeMaxDynamicSharedMemorySize, SMEM_BYTES);
  dim3 grid(NQ / BM, Bb, NSPLIT);
  attn_mma_kernel<<<grid, THREADS, SMEM_BYTES>>>(Q, MQ);

  combine_kernel<<<(Bb * NQ * DV / 4) / 256, 256>>>(Out);
}

// round 16
// speedup vs baseline: 3.5075x; 1.3394x over previous
#include <cuda_runtime.h>
#include <cuda_fp16.h>
#include <cstdint>

// ============================================================
// R16: mask-compacted flash attention.
//  Masked queries (mq=0): output = mean of valid V (exact, per batch).
//  Masked keys  (mk=0): compacted out of K/V before the GEMMs.
//  => GEMM work ~25% of dense. Pipeline:
//   scan    : per-batch valid key/query index lists + counts
//   gather  : compacted K,V -> fp16 swizzled tiles (+MC: col0=1 real,0 pad)
//   meanv   : per-batch mean of valid V (for masked-query rows)
//   attn    : compacted warp-MMA flash attn, dynamic tile counts,
//             split-K=4, 3-stage cp.async, l via mask-column MMA
//   combine : scatter valid-query slots, Out = sum O_z / sum l_z
//   fill    : masked-query rows <- meanV
// ============================================================

namespace {
constexpr int NQ = 4096, NK = 4096, D = 64, DV = 64, Bb = 8;
constexpr int BM = 128, BN = 64, THREADS = 256;
constexpr int NSPLIT = 4;
constexpr float QSCALE = 0.18033688011112042f;  // log2(e) / 8

constexpr int ST_K = 0, ST_V = 8192, ST_MC = 16384;
constexpr int STAGE = 17408;
constexpr int NSTAGE = 3;
constexpr int SMEM_BYTES = NSTAGE * STAGE;      // 52224
}

__device__ __align__(16) uint8_t g_K16[(size_t)Bb * NK * D * 2];
__device__ __align__(16) uint8_t g_V16[(size_t)Bb * NK * DV * 2];
__device__ __align__(16) uint8_t g_MC[(size_t)Bb * NK * 16];
__device__ __align__(16) float   g_Op[(size_t)NSPLIT * Bb * NQ * DV];
__device__ __align__(16) float   g_lp[(size_t)NSPLIT * Bb * NQ];
__device__ __align__(16) float   g_meanV[Bb * DV];
__device__ int g_kidx[Bb * NK];
__device__ int g_qidx[Bb * NQ];
__device__ int g_nk[Bb];
__device__ int g_nq[Bb];

__device__ __forceinline__ uint32_t smem_u32(const void* p) {
  uint32_t a;
  asm("{ .reg .u64 t; cvta.to.shared.u64 t, %1; cvt.u32.u64 %0, t; }" : "=r"(a) : "l"(p));
  return a;
}
__device__ __forceinline__ uint32_t pack2h(float x, float y) {
  __half2 h = __floats2half2_rn(x, y);
  return *reinterpret_cast<uint32_t*>(&h);
}
__device__ __forceinline__ float ex2f(float x) {
  float y;
  asm("ex2.approx.ftz.f32 %0, %1;" : "=f"(y) : "f"(x));
  return y;
}
__device__ __forceinline__ void mma16816(float* c, const uint32_t* a,
                                         uint32_t b0, uint32_t b1) {
  asm("mma.sync.aligned.m16n8k16.row.col.f32.f16.f16.f32 "
      "{%0,%1,%2,%3}, {%4,%5,%6,%7}, {%8,%9}, {%0,%1,%2,%3};"
      : "+f"(c[0]), "+f"(c[1]), "+f"(c[2]), "+f"(c[3])
      : "r"(a[0]), "r"(a[1]), "r"(a[2]), "r"(a[3]), "r"(b0), "r"(b1));
}
__device__ __forceinline__ void ldsm4(uint32_t a, uint32_t* d) {
  asm volatile("ldmatrix.sync.aligned.m8n8.x4.shared.b16 {%0,%1,%2,%3}, [%4];"
               : "=r"(d[0]), "=r"(d[1]), "=r"(d[2]), "=r"(d[3]) : "r"(a));
}
__device__ __forceinline__ void ldsm4t(uint32_t a, uint32_t* d) {
  asm volatile("ldmatrix.sync.aligned.m8n8.x4.trans.shared.b16 {%0,%1,%2,%3}, [%4];"
               : "=r"(d[0]), "=r"(d[1]), "=r"(d[2]), "=r"(d[3]) : "r"(a));
}
__device__ __forceinline__ void cpasync16(uint32_t dst, const void* src) {
  asm volatile("cp.async.cg.shared.global [%0], [%1], 16;"
               :: "r"(dst), "l"(src) : "memory");
}
#define CP_COMMIT() asm volatile("cp.async.commit_group;" ::: "memory")
#define CP_WAIT1()  asm volatile("cp.async.wait_group 1;"  ::: "memory")

__device__ __forceinline__ uint32_t swz(uint32_t r, uint32_t cbyte) {
  return r * 128u + (cbyte ^ ((r & 7u) * 16u));
}

// ---------------- scan: valid-index lists + counts ----------------
__global__ __launch_bounds__(1024)
void scan_kernel(const int* __restrict__ MQ, const int* __restrict__ MK) {
  const int b = blockIdx.x, t = threadIdx.x;
  const int lane = t & 31, wid = t >> 5;
  __shared__ int wsum[32];
  #pragma unroll
  for (int which = 0; which < 2; which++) {
    const int* M = (which ? MQ : MK) + (size_t)b * 4096;
    int* out = (which ? g_qidx : g_kidx) + b * 4096;
    int v[4], s = 0;
    #pragma unroll
    for (int i = 0; i < 4; i++) { v[i] = M[t * 4 + i]; s += v[i]; }
    int inc = s;
    #pragma unroll
    for (int d = 1; d < 32; d <<= 1) {
      int n = __shfl_up_sync(0xffffffffu, inc, d);
      if (lane >= d) inc += n;
    }
    if (lane == 31) wsum[wid] = inc;
    __syncthreads();
    if (wid == 0) {
      int ws = wsum[lane];
      #pragma unroll
      for (int d = 1; d < 32; d <<= 1) {
        int n = __shfl_up_sync(0xffffffffu, ws, d);
        if (lane >= d) ws += n;
      }
      wsum[lane] = ws;
    }
    __syncthreads();
    int base = (wid > 0 ? wsum[wid - 1] : 0) + inc - s;   // exclusive prefix
    #pragma unroll
    for (int i = 0; i < 4; i++)
      if (v[i]) out[base++] = t * 4 + i;
    __syncthreads();                    // global writes visible block-wide
    if (t == 0) {
      const int total = wsum[31];
      if (which) {
        g_nq[b] = total;
        const int first = out[0];
        const int pad = (total + 127) & ~127;
        for (int i = total; i < pad; i++) out[i] = first;   // duplicate pads
      } else {
        g_nk[b] = total;
      }
    }
    __syncthreads();
  }
}

// ---------------- gather: compacted K,V -> fp16 swizzled tiles ----------------
__global__ __launch_bounds__(256)
void gather_kernel(const float* __restrict__ K, const float* __restrict__ V) {
  const int idx = blockIdx.x * 256 + threadIdx.x;   // (b, slot, c4)
  const int b = idx >> 16;
  const int slot = (idx >> 4) & 4095;
  const int c4 = idx & 15;
  const int nk = g_nk[b];
  const int nk64 = (nk + 63) & ~63;
  if (slot >= nk64) return;

  const uint32_t r = (uint32_t)(slot & 63);
  const size_t off = (size_t)(b * 64 + (slot >> 6)) * 8192 + swz(r, (uint32_t)c4 * 8u);
  uint2 wk = make_uint2(0u, 0u), wv = make_uint2(0u, 0u);
  if (slot < nk) {
    const int key = g_kidx[b * 4096 + slot];
    const float4 kv = reinterpret_cast<const float4*>(K + ((size_t)b * NK + key) * D)[c4];
    wk.x = pack2h(kv.x, kv.y); wk.y = pack2h(kv.z, kv.w);
    const float4 vv = reinterpret_cast<const float4*>(V + ((size_t)b * NK + key) * DV)[c4];
    wv.x = pack2h(vv.x, vv.y); wv.y = pack2h(vv.z, vv.w);
  }
  *reinterpret_cast<uint2*>(g_K16 + off) = wk;
  *reinterpret_cast<uint2*>(g_V16 + off) = wv;
  if (c4 == 0) {
    uint4 mc;
    mc.x = pack2h(slot < nk ? 1.f : 0.f, 0.f);
    mc.y = 0u; mc.z = 0u; mc.w = 0u;
    *reinterpret_cast<uint4*>(g_MC + (size_t)(b * 4096 + slot) * 16) = mc;
  }
}

// ---------------- meanv: per-batch mean of valid V ----------------
__global__ __launch_bounds__(256)
void meanv_kernel(const float* __restrict__ V, const int* __restrict__ MK) {
  const int b = blockIdx.x, t = threadIdx.x;
  const int dim = t & 63, grp = t >> 6;
  __shared__ float red[256];
  float acc = 0.f;
  for (int key = grp; key < NK; key += 4)
    acc += (float)MK[b * NK + key] * V[((size_t)b * NK + key) * DV + dim];
  red[t] = acc;
  __syncthreads();
  if (t < 64) {
    const float s = red[t] + red[t + 64] + red[t + 128] + red[t + 192];
    g_meanV[b * DV + t] = s / (float)g_nk[b];
  }
}

// ---------------- main attention kernel (compacted) ----------------
__global__ __launch_bounds__(THREADS, 2)
void attn_mma_kernel(const float* __restrict__ Q) {
  extern __shared__ char smem[];
  const uint32_t sb = smem_u32(smem);

  const int tid = threadIdx.x;
  const int w = tid >> 5, l = tid & 31;
  const int g = l >> 2, tg = l & 3;
  const int b = blockIdx.y;
  const int kq = blockIdx.z;
  const int q0 = blockIdx.x * BM;

  const int nq = g_nq[b];
  const int nqp = (nq + 127) & ~127;
  if (q0 >= nqp) return;
  const int nk = g_nk[b];
  const int ntiles = (nk + 63) >> 6;
  const int tq = (ntiles + 3) >> 2;
  const int lo = kq * tq;
  const int hi = min(lo + tq, ntiles);

  const int qs0 = q0 + w * 16 + g;                 // query SLOT for row0
  const int row0 = g_qidx[b * 4096 + qs0];
  const int row1 = g_qidx[b * 4096 + qs0 + 8];
  const uint32_t lrow = (uint32_t)(l & 7);
  const uint32_t ltile = (uint32_t)(l >> 3);

  // ---- Q fragments: fp16 of q * log2e/T (all compacted queries valid)
  uint32_t QH[4][4];
  {
    const float* Qr0 = Q + ((size_t)b * NQ + row0) * D;
    const float* Qr1 = Q + ((size_t)b * NQ + row1) * D;
    #pragma unroll
    for (int ks = 0; ks < 4; ks++) {
      const int c = 16 * ks + 2 * tg;
      float2 v00 = *reinterpret_cast<const float2*>(Qr0 + c);
      float2 v10 = *reinterpret_cast<const float2*>(Qr1 + c);
      float2 v01 = *reinterpret_cast<const float2*>(Qr0 + c + 8);
      float2 v11 = *reinterpret_cast<const float2*>(Qr1 + c + 8);
      QH[ks][0] = pack2h(v00.x * QSCALE, v00.y * QSCALE);
      QH[ks][1] = pack2h(v10.x * QSCALE, v10.y * QSCALE);
      QH[ks][2] = pack2h(v01.x * QSCALE, v01.y * QSCALE);
      QH[ks][3] = pack2h(v11.x * QSCALE, v11.y * QSCALE);
    }
  }

  float O[8][4], Ol[4];
  #pragma unroll
  for (int i = 0; i < 8; i++)
    #pragma unroll
    for (int j = 0; j < 4; j++) O[i][j] = 0.f;
  #pragma unroll
  for (int j = 0; j < 4; j++) Ol[j] = 0.f;

  auto prefetch = [&](int t, int s) {
    const uint32_t dst = sb + (uint32_t)s * STAGE;
    const size_t toff = (size_t)(b * 64 + t) * 8192;
    #pragma unroll
    for (int i = 0; i < 2; i++) {
      const uint32_t o = (uint32_t)(tid + i * THREADS) * 16u;
      cpasync16(dst + ST_K + o, g_K16 + toff + o);
      cpasync16(dst + ST_V + o, g_V16 + toff + o);
    }
    if (tid < 64)
      cpasync16(dst + ST_MC + tid * 16u,
                g_MC + (size_t)(b * 64 + t) * 1024 + tid * 16u);
  };

  if (lo < hi) prefetch(lo, 0);
  CP_COMMIT();
  if (lo + 1 < hi) prefetch(lo + 1, 1);
  CP_COMMIT();

  int st = 0;
  for (int t = lo; t < hi; t++) {
    CP_WAIT1();
    __syncthreads();

    int s2 = st + 2; if (s2 >= NSTAGE) s2 -= NSTAGE;
    if (t + 2 < hi) prefetch(t + 2, s2);
    CP_COMMIT();

    const uint32_t skh = sb + (uint32_t)st * STAGE + ST_K;
    const uint32_t svh = sb + (uint32_t)st * STAGE + ST_V;
    const uint32_t smc = sb + (uint32_t)st * STAGE + ST_MC;

    float S[8][4];
    #pragma unroll
    for (int i = 0; i < 8; i++)
      #pragma unroll
      for (int j = 0; j < 4; j++) S[i][j] = 0.f;

    // ---- S = Q16 @ K16^T  (pad-key rows: K=0 -> S=0 -> p=1, harmless)
    #pragma unroll
    for (int nf = 0; nf < 8; nf++) {
      const uint32_t n = 8u * nf + lrow;
      const uint32_t a0 = swz(n, (8u * ltile) * 2u);
      const uint32_t a1 = swz(n, (32u + 8u * ltile) * 2u);
      uint32_t f[8];
      ldsm4(skh + a0, f);
      ldsm4(skh + a1, f + 4);
      #pragma unroll
      for (int ks = 0; ks < 4; ks++)
        mma16816(S[nf], QH[ks], f[2 * ks], f[2 * ks + 1]);
    }

    // ---- two half-chunks: p = exp2(S); pack; PV + l-column MMA
    #pragma unroll
    for (int ch = 0; ch < 2; ch++) {
      float* Sc = &S[4 * ch][0];

      #pragma unroll
      for (int j = 0; j < 16; j++) Sc[j] = ex2f(Sc[j]);

      uint32_t PH[2][4];
      #pragma unroll
      for (int j = 0; j < 2; j++) {
        PH[j][0] = pack2h(Sc[8 * j + 0], Sc[8 * j + 1]);
        PH[j][1] = pack2h(Sc[8 * j + 2], Sc[8 * j + 3]);
        PH[j][2] = pack2h(Sc[8 * j + 4], Sc[8 * j + 5]);
        PH[j][3] = pack2h(Sc[8 * j + 6], Sc[8 * j + 7]);
      }

      const uint32_t vr = 32u * ch + 8u * ltile + lrow;

      uint32_t fm[4];
      ldsm4t(smc + vr * 16u, fm);
      #pragma unroll
      for (int j = 0; j < 2; j++)
        mma16816(Ol, PH[j], fm[2 * j], fm[2 * j + 1]);

      #pragma unroll
      for (int nf = 0; nf < 8; nf++) {
        const uint32_t a = swz(vr, 16u * nf);
        uint32_t fh[4];
        ldsm4t(svh + a, fh);
        #pragma unroll
        for (int j = 0; j < 2; j++)
          mma16816(O[nf], PH[j], fh[2 * j], fh[2 * j + 1]);
      }
    }
    if (++st == NSTAGE) st = 0;
  }

  // ---- write unnormalized partials + l, indexed by query SLOT
  const size_t pbase = (size_t)kq * Bb * NQ;
  float* O0 = g_Op + (pbase + (size_t)b * NQ + qs0) * DV;
  float* O1 = g_Op + (pbase + (size_t)b * NQ + qs0 + 8) * DV;
  #pragma unroll
  for (int nf = 0; nf < 8; nf++) {
    const int c = 8 * nf + 2 * tg;
    *reinterpret_cast<float2*>(O0 + c) = make_float2(O[nf][0], O[nf][1]);
    *reinterpret_cast<float2*>(O1 + c) = make_float2(O[nf][2], O[nf][3]);
  }
  if (tg == 0) {
    g_lp[pbase + (size_t)b * NQ + qs0] = Ol[0];
    g_lp[pbase + (size_t)b * NQ + qs0 + 8] = Ol[2];
  }
}

// ---------------- combine: scatter valid slots ----------------
__global__ __launch_bounds__(256)
void combine_kernel(float* __restrict__ Out) {
  const int idx = blockIdx.x * 256 + threadIdx.x;   // float4 over slots
  const int slot = idx >> 4;                        // b*4096 + s
  const int b = slot >> 12;
  const int sl = slot & 4095;
  if (sl >= g_nq[b]) return;
  const int row = g_qidx[slot];
  float4 acc = make_float4(0.f, 0.f, 0.f, 0.f);
  float lsum = 0.f;
  #pragma unroll
  for (int z = 0; z < NSPLIT; z++) {
    float4 v = reinterpret_cast<const float4*>(g_Op)[(size_t)z * Bb * NQ * (DV / 4) + idx];
    acc.x += v.x; acc.y += v.y; acc.z += v.z; acc.w += v.w;
    lsum += g_lp[(size_t)z * Bb * NQ + slot];
  }
  const float inv = 1.0f / lsum;
  acc.x *= inv; acc.y *= inv; acc.z *= inv; acc.w *= inv;
  reinterpret_cast<float4*>(Out + ((size_t)b * NQ + row) * DV)[idx & 15] = acc;
}

// ---------------- fill: masked-query rows <- meanV ----------------
__global__ __launch_bounds__(256)
void fill_kernel(const int* __restrict__ MQ, float* __restrict__ Out) {
  const int idx = blockIdx.x * 256 + threadIdx.x;   // float4 over all rows
  const int grow = idx >> 4;
  if (MQ[grow] == 0) {
    const int b = grow >> 12;
    float4 mv = reinterpret_cast<const float4*>(g_meanV + b * DV)[idx & 15];
    reinterpret_cast<float4*>(Out)[idx] = mv;
  }
}

extern "C" void kernel_launch(void* const* d_in, const int* in_sizes, int n_in,
                              void* d_out, int out_size) {
  (void)in_sizes; (void)n_in; (void)out_size;
  const float* Q  = (const float*)d_in[0];
  const float* K  = (const float*)d_in[1];
  const float* V  = (const float*)d_in[2];
  const int*   MQ = (const int*)d_in[3];
  const int*   MK = (const int*)d_in[4];
  float* Out = (float*)d_out;

  scan_kernel<<<Bb, 1024>>>(MQ, MK);
  gather_kernel<<<(Bb * NK * 16) / 256, 256>>>(K, V);
  meanv_kernel<<<Bb, 256>>>(V, MK);

  cudaFuncSetAttribute(attn_mma_kernel,
                       cudaFuncAttributeMaxDynamicSharedMemorySize, SMEM_BYTES);
  dim3 grid(NQ / BM, Bb, NSPLIT);
  attn_mma_kernel<<<grid, THREADS, SMEM_BYTES>>>(Q);

  combine_kernel<<<(Bb * NQ * 16) / 256, 256>>>(Out);
  fill_kernel<<<(Bb * NQ * 16) / 256, 256>>>(MQ, Out);
}

// round 17
// speedup vs baseline: 4.1951x; 1.1960x over previous
#include <cuda_runtime.h>
#include <cuda_fp16.h>
#include <cstdint>

// ============================================================
// R17: shrink the fixed pipeline around the compacted attention.
//  - meanv now reads the compacted fp16 V16 tiles (2 MB) instead of
//    dense fp32 V (32 MB).
//  - combine+fill fused into one row-indexed finalize kernel using an
//    inverse query-slot map written by scan.
// Attention mainloop unchanged from R16 (82.8 us, attn 38 us).
// ============================================================

namespace {
constexpr int NQ = 4096, NK = 4096, D = 64, DV = 64, Bb = 8;
constexpr int BM = 128, BN = 64, THREADS = 256;
constexpr int NSPLIT = 4;
constexpr float QSCALE = 0.18033688011112042f;  // log2(e) / 8

constexpr int ST_K = 0, ST_V = 8192, ST_MC = 16384;
constexpr int STAGE = 17408;
constexpr int NSTAGE = 3;
constexpr int SMEM_BYTES = NSTAGE * STAGE;      // 52224
}

__device__ __align__(16) uint8_t g_K16[(size_t)Bb * NK * D * 2];
__device__ __align__(16) uint8_t g_V16[(size_t)Bb * NK * DV * 2];
__device__ __align__(16) uint8_t g_MC[(size_t)Bb * NK * 16];
__device__ __align__(16) float   g_Op[(size_t)NSPLIT * Bb * NQ * DV];
__device__ __align__(16) float   g_lp[(size_t)NSPLIT * Bb * NQ];
__device__ __align__(16) float   g_meanV[Bb * DV];
__device__ int g_kidx[Bb * NK];
__device__ int g_qidx[Bb * NQ];
__device__ int g_qslot[Bb * NQ];
__device__ int g_nk[Bb];
__device__ int g_nq[Bb];

__device__ __forceinline__ uint32_t smem_u32(const void* p) {
  uint32_t a;
  asm("{ .reg .u64 t; cvta.to.shared.u64 t, %1; cvt.u32.u64 %0, t; }" : "=r"(a) : "l"(p));
  return a;
}
__device__ __forceinline__ uint32_t pack2h(float x, float y) {
  __half2 h = __floats2half2_rn(x, y);
  return *reinterpret_cast<uint32_t*>(&h);
}
__device__ __forceinline__ float ex2f(float x) {
  float y;
  asm("ex2.approx.ftz.f32 %0, %1;" : "=f"(y) : "f"(x));
  return y;
}
__device__ __forceinline__ void mma16816(float* c, const uint32_t* a,
                                         uint32_t b0, uint32_t b1) {
  asm("mma.sync.aligned.m16n8k16.row.col.f32.f16.f16.f32 "
      "{%0,%1,%2,%3}, {%4,%5,%6,%7}, {%8,%9}, {%0,%1,%2,%3};"
      : "+f"(c[0]), "+f"(c[1]), "+f"(c[2]), "+f"(c[3])
      : "r"(a[0]), "r"(a[1]), "r"(a[2]), "r"(a[3]), "r"(b0), "r"(b1));
}
__device__ __forceinline__ void ldsm4(uint32_t a, uint32_t* d) {
  asm volatile("ldmatrix.sync.aligned.m8n8.x4.shared.b16 {%0,%1,%2,%3}, [%4];"
               : "=r"(d[0]), "=r"(d[1]), "=r"(d[2]), "=r"(d[3]) : "r"(a));
}
__device__ __forceinline__ void ldsm4t(uint32_t a, uint32_t* d) {
  asm volatile("ldmatrix.sync.aligned.m8n8.x4.trans.shared.b16 {%0,%1,%2,%3}, [%4];"
               : "=r"(d[0]), "=r"(d[1]), "=r"(d[2]), "=r"(d[3]) : "r"(a));
}
__device__ __forceinline__ void cpasync16(uint32_t dst, const void* src) {
  asm volatile("cp.async.cg.shared.global [%0], [%1], 16;"
               :: "r"(dst), "l"(src) : "memory");
}
#define CP_COMMIT() asm volatile("cp.async.commit_group;" ::: "memory")
#define CP_WAIT1()  asm volatile("cp.async.wait_group 1;"  ::: "memory")

__device__ __forceinline__ uint32_t swz(uint32_t r, uint32_t cbyte) {
  return r * 128u + (cbyte ^ ((r & 7u) * 16u));
}

// ---------------- scan: index lists + counts + inverse query map ----------------
__global__ __launch_bounds__(1024)
void scan_kernel(const int* __restrict__ MQ, const int* __restrict__ MK) {
  const int b = blockIdx.x, t = threadIdx.x;
  const int lane = t & 31, wid = t >> 5;
  __shared__ int wsum[32];
  #pragma unroll
  for (int which = 0; which < 2; which++) {
    const int* M = (which ? MQ : MK) + (size_t)b * 4096;
    int* out = (which ? g_qidx : g_kidx) + b * 4096;
    int v[4], s = 0;
    #pragma unroll
    for (int i = 0; i < 4; i++) { v[i] = M[t * 4 + i]; s += v[i]; }
    int inc = s;
    #pragma unroll
    for (int d = 1; d < 32; d <<= 1) {
      int n = __shfl_up_sync(0xffffffffu, inc, d);
      if (lane >= d) inc += n;
    }
    if (lane == 31) wsum[wid] = inc;
    __syncthreads();
    if (wid == 0) {
      int ws = wsum[lane];
      #pragma unroll
      for (int d = 1; d < 32; d <<= 1) {
        int n = __shfl_up_sync(0xffffffffu, ws, d);
        if (lane >= d) ws += n;
      }
      wsum[lane] = ws;
    }
    __syncthreads();
    int base = (wid > 0 ? wsum[wid - 1] : 0) + inc - s;   // exclusive prefix
    #pragma unroll
    for (int i = 0; i < 4; i++)
      if (v[i]) {
        const int row = t * 4 + i;
        if (which) g_qslot[b * 4096 + row] = base;
        out[base++] = row;
      }
    __syncthreads();
    if (t == 0) {
      const int total = wsum[31];
      if (which) {
        g_nq[b] = total;
        const int first = out[0];
        const int pad = (total + 127) & ~127;
        for (int i = total; i < pad; i++) out[i] = first;   // duplicate pads
      } else {
        g_nk[b] = total;
      }
    }
    __syncthreads();
  }
}

// ---------------- gather: compacted K,V -> fp16 swizzled tiles ----------------
__global__ __launch_bounds__(256)
void gather_kernel(const float* __restrict__ K, const float* __restrict__ V) {
  const int idx = blockIdx.x * 256 + threadIdx.x;   // (b, slot, c4)
  const int b = idx >> 16;
  const int slot = (idx >> 4) & 4095;
  const int c4 = idx & 15;
  const int nk = g_nk[b];
  const int nk64 = (nk + 63) & ~63;
  if (slot >= nk64) return;

  const uint32_t r = (uint32_t)(slot & 63);
  const size_t off = (size_t)(b * 64 + (slot >> 6)) * 8192 + swz(r, (uint32_t)c4 * 8u);
  uint2 wk = make_uint2(0u, 0u), wv = make_uint2(0u, 0u);
  if (slot < nk) {
    const int key = g_kidx[b * 4096 + slot];
    const float4 kv = reinterpret_cast<const float4*>(K + ((size_t)b * NK + key) * D)[c4];
    wk.x = pack2h(kv.x, kv.y); wk.y = pack2h(kv.z, kv.w);
    const float4 vv = reinterpret_cast<const float4*>(V + ((size_t)b * NK + key) * DV)[c4];
    wv.x = pack2h(vv.x, vv.y); wv.y = pack2h(vv.z, vv.w);
  }
  *reinterpret_cast<uint2*>(g_K16 + off) = wk;
  *reinterpret_cast<uint2*>(g_V16 + off) = wv;
  if (c4 == 0) {
    uint4 mc;
    mc.x = pack2h(slot < nk ? 1.f : 0.f, 0.f);
    mc.y = 0u; mc.z = 0u; mc.w = 0u;
    *reinterpret_cast<uint4*>(g_MC + (size_t)(b * 4096 + slot) * 16) = mc;
  }
}

// ---------------- meanv: per-batch mean of valid V, from compacted V16 ----------------
__global__ __launch_bounds__(256)
void meanv_kernel() {
  const int b = blockIdx.x, t = threadIdx.x;
  const int cell = t >> 5;        // 0..7: dims 8*cell .. 8*cell+7 (one 16B unit)
  const int grp = t & 31;
  __shared__ float red[8][32][8];
  const int nk64 = (g_nk[b] + 63) & ~63;

  float acc[8];
  #pragma unroll
  for (int j = 0; j < 8; j++) acc[j] = 0.f;
  for (int r = grp; r < nk64; r += 32) {          // pad rows are zero: safe
    const size_t off = (size_t)(b * 64 + (r >> 6)) * 8192 +
                       swz((uint32_t)(r & 63), (uint32_t)cell * 16u);
    uint4 wv = *reinterpret_cast<const uint4*>(g_V16 + off);
    const uint32_t* wp = &wv.x;
    #pragma unroll
    for (int k = 0; k < 4; k++) {
      __half2 h = *reinterpret_cast<const __half2*>(&wp[k]);
      float2 f = __half22float2(h);
      acc[2 * k] += f.x;
      acc[2 * k + 1] += f.y;
    }
  }
  #pragma unroll
  for (int j = 0; j < 8; j++) red[cell][grp][j] = acc[j];
  __syncthreads();
  if (t < 64) {
    const int c = t >> 3, j = t & 7;
    float s = 0.f;
    #pragma unroll
    for (int gx = 0; gx < 32; gx++) s += red[c][gx][j];
    g_meanV[b * DV + c * 8 + j] = s / (float)g_nk[b];
  }
}

// ---------------- main attention kernel (compacted) ----------------
__global__ __launch_bounds__(THREADS, 2)
void attn_mma_kernel(const float* __restrict__ Q) {
  extern __shared__ char smem[];
  const uint32_t sb = smem_u32(smem);

  const int tid = threadIdx.x;
  const int w = tid >> 5, l = tid & 31;
  const int g = l >> 2, tg = l & 3;
  const int b = blockIdx.y;
  const int kq = blockIdx.z;
  const int q0 = blockIdx.x * BM;

  const int nq = g_nq[b];
  const int nqp = (nq + 127) & ~127;
  if (q0 >= nqp) return;
  const int nk = g_nk[b];
  const int ntiles = (nk + 63) >> 6;
  const int tq = (ntiles + 3) >> 2;
  const int lo = kq * tq;
  const int hi = min(lo + tq, ntiles);

  const int qs0 = q0 + w * 16 + g;                 // query SLOT for row0
  const int row0 = g_qidx[b * 4096 + qs0];
  const int row1 = g_qidx[b * 4096 + qs0 + 8];
  const uint32_t lrow = (uint32_t)(l & 7);
  const uint32_t ltile = (uint32_t)(l >> 3);

  uint32_t QH[4][4];
  {
    const float* Qr0 = Q + ((size_t)b * NQ + row0) * D;
    const float* Qr1 = Q + ((size_t)b * NQ + row1) * D;
    #pragma unroll
    for (int ks = 0; ks < 4; ks++) {
      const int c = 16 * ks + 2 * tg;
      float2 v00 = *reinterpret_cast<const float2*>(Qr0 + c);
      float2 v10 = *reinterpret_cast<const float2*>(Qr1 + c);
      float2 v01 = *reinterpret_cast<const float2*>(Qr0 + c + 8);
      float2 v11 = *reinterpret_cast<const float2*>(Qr1 + c + 8);
      QH[ks][0] = pack2h(v00.x * QSCALE, v00.y * QSCALE);
      QH[ks][1] = pack2h(v10.x * QSCALE, v10.y * QSCALE);
      QH[ks][2] = pack2h(v01.x * QSCALE, v01.y * QSCALE);
      QH[ks][3] = pack2h(v11.x * QSCALE, v11.y * QSCALE);
    }
  }

  float O[8][4], Ol[4];
  #pragma unroll
  for (int i = 0; i < 8; i++)
    #pragma unroll
    for (int j = 0; j < 4; j++) O[i][j] = 0.f;
  #pragma unroll
  for (int j = 0; j < 4; j++) Ol[j] = 0.f;

  auto prefetch = [&](int t, int s) {
    const uint32_t dst = sb + (uint32_t)s * STAGE;
    const size_t toff = (size_t)(b * 64 + t) * 8192;
    #pragma unroll
    for (int i = 0; i < 2; i++) {
      const uint32_t o = (uint32_t)(tid + i * THREADS) * 16u;
      cpasync16(dst + ST_K + o, g_K16 + toff + o);
      cpasync16(dst + ST_V + o, g_V16 + toff + o);
    }
    if (tid < 64)
      cpasync16(dst + ST_MC + tid * 16u,
                g_MC + (size_t)(b * 64 + t) * 1024 + tid * 16u);
  };

  if (lo < hi) prefetch(lo, 0);
  CP_COMMIT();
  if (lo + 1 < hi) prefetch(lo + 1, 1);
  CP_COMMIT();

  int st = 0;
  for (int t = lo; t < hi; t++) {
    CP_WAIT1();
    __syncthreads();

    int s2 = st + 2; if (s2 >= NSTAGE) s2 -= NSTAGE;
    if (t + 2 < hi) prefetch(t + 2, s2);
    CP_COMMIT();

    const uint32_t skh = sb + (uint32_t)st * STAGE + ST_K;
    const uint32_t svh = sb + (uint32_t)st * STAGE + ST_V;
    const uint32_t smc = sb + (uint32_t)st * STAGE + ST_MC;

    float S[8][4];
    #pragma unroll
    for (int i = 0; i < 8; i++)
      #pragma unroll
      for (int j = 0; j < 4; j++) S[i][j] = 0.f;

    #pragma unroll
    for (int nf = 0; nf < 8; nf++) {
      const uint32_t n = 8u * nf + lrow;
      const uint32_t a0 = swz(n, (8u * ltile) * 2u);
      const uint32_t a1 = swz(n, (32u + 8u * ltile) * 2u);
      uint32_t f[8];
      ldsm4(skh + a0, f);
      ldsm4(skh + a1, f + 4);
      #pragma unroll
      for (int ks = 0; ks < 4; ks++)
        mma16816(S[nf], QH[ks], f[2 * ks], f[2 * ks + 1]);
    }

    #pragma unroll
    for (int ch = 0; ch < 2; ch++) {
      float* Sc = &S[4 * ch][0];

      #pragma unroll
      for (int j = 0; j < 16; j++) Sc[j] = ex2f(Sc[j]);

      uint32_t PH[2][4];
      #pragma unroll
      for (int j = 0; j < 2; j++) {
        PH[j][0] = pack2h(Sc[8 * j + 0], Sc[8 * j + 1]);
        PH[j][1] = pack2h(Sc[8 * j + 2], Sc[8 * j + 3]);
        PH[j][2] = pack2h(Sc[8 * j + 4], Sc[8 * j + 5]);
        PH[j][3] = pack2h(Sc[8 * j + 6], Sc[8 * j + 7]);
      }

      const uint32_t vr = 32u * ch + 8u * ltile + lrow;

      uint32_t fm[4];
      ldsm4t(smc + vr * 16u, fm);
      #pragma unroll
      for (int j = 0; j < 2; j++)
        mma16816(Ol, PH[j], fm[2 * j], fm[2 * j + 1]);

      #pragma unroll
      for (int nf = 0; nf < 8; nf++) {
        const uint32_t a = swz(vr, 16u * nf);
        uint32_t fh[4];
        ldsm4t(svh + a, fh);
        #pragma unroll
        for (int j = 0; j < 2; j++)
          mma16816(O[nf], PH[j], fh[2 * j], fh[2 * j + 1]);
      }
    }
    if (++st == NSTAGE) st = 0;
  }

  // ---- write unnormalized partials + l, indexed by query SLOT
  const size_t pbase = (size_t)kq * Bb * NQ;
  float* O0 = g_Op + (pbase + (size_t)b * NQ + qs0) * DV;
  float* O1 = g_Op + (pbase + (size_t)b * NQ + qs0 + 8) * DV;
  #pragma unroll
  for (int nf = 0; nf < 8; nf++) {
    const int c = 8 * nf + 2 * tg;
    *reinterpret_cast<float2*>(O0 + c) = make_float2(O[nf][0], O[nf][1]);
    *reinterpret_cast<float2*>(O1 + c) = make_float2(O[nf][2], O[nf][3]);
  }
  if (tg == 0) {
    g_lp[pbase + (size_t)b * NQ + qs0] = Ol[0];
    g_lp[pbase + (size_t)b * NQ + qs0 + 8] = Ol[2];
  }
}

// ---------------- finalize: combine + fill fused, row-indexed ----------------
__global__ __launch_bounds__(256)
void finalize_kernel(const int* __restrict__ MQ, float* __restrict__ Out) {
  const int idx = blockIdx.x * 256 + threadIdx.x;   // float4 over all rows
  const int grow = idx >> 4;                        // b*NQ + row
  const int b = grow >> 12;
  float4 res;
  if (MQ[grow] == 0) {
    res = reinterpret_cast<const float4*>(g_meanV + b * DV)[idx & 15];
  } else {
    const int slot = b * 4096 + g_qslot[grow];
    float4 acc = make_float4(0.f, 0.f, 0.f, 0.f);
    float lsum = 0.f;
    #pragma unroll
    for (int z = 0; z < NSPLIT; z++) {
      float4 v = reinterpret_cast<const float4*>(
          g_Op + ((size_t)z * Bb * NQ + slot) * DV)[idx & 15];
      acc.x += v.x; acc.y += v.y; acc.z += v.z; acc.w += v.w;
      lsum += g_lp[(size_t)z * Bb * NQ + slot];
    }
    const float inv = 1.0f / lsum;
    res = make_float4(acc.x * inv, acc.y * inv, acc.z * inv, acc.w * inv);
  }
  reinterpret_cast<float4*>(Out)[idx] = res;
}

extern "C" void kernel_launch(void* const* d_in, const int* in_sizes, int n_in,
                              void* d_out, int out_size) {
  (void)in_sizes; (void)n_in; (void)out_size;
  const float* Q  = (const float*)d_in[0];
  const float* K  = (const float*)d_in[1];
  const float* V  = (const float*)d_in[2];
  const int*   MQ = (const int*)d_in[3];
  const int*   MK = (const int*)d_in[4];
  float* Out = (float*)d_out;

  scan_kernel<<<Bb, 1024>>>(MQ, MK);
  gather_kernel<<<(Bb * NK * 16) / 256, 256>>>(K, V);
  meanv_kernel<<<Bb, 256>>>();

  cudaFuncSetAttribute(attn_mma_kernel,
                       cudaFuncAttributeMaxDynamicSharedMemorySize, SMEM_BYTES);
  dim3 grid(NQ / BM, Bb, NSPLIT);
  attn_mma_kernel<<<grid, THREADS, SMEM_BYTES>>>(Q);

  finalize_kernel<<<(Bb * NQ * 16) / 256, 256>>>(MQ, Out);
}